// round 1
// baseline (speedup 1.0000x reference)
#include <cuda_runtime.h>

#define EPS 1e-8f
#define BN 4
#define CN 128
#define HN 256
#define WN 256
#define HW (HN*WN)       // 65536
#define NCH (BN*CN)      // 512
#define MHW (128*128)    // 16384

// Scratch (no allocations allowed): per-channel partial sums + final coefficients.
__device__ float g_sums[NCH * 12];
__device__ float g_coef[NCH * 4];

__device__ __forceinline__ float warpSum(float v) {
#pragma unroll
    for (int o = 16; o; o >>= 1) v += __shfl_xor_sync(0xffffffffu, v, o);
    return v;
}

// ---------------------------------------------------------------------------
// Kernel 1: per-(b,c) reductions over HW.
// For each tensor (x1,x2) and each region (m, 1-m) accumulate:
//   A = sum x*m,  B = sum x*m^3,  C = sum x^2*m^4   (var = (C - 2*mu*B + mu^2*Sum m^2)/n)
// One block per channel, 256 threads, float4 loads, mask loaded as float2
// (2x2 nearest upsample => two distinct mask values per float4 of x).
// ---------------------------------------------------------------------------
__global__ __launch_bounds__(256) void k_reduce(const float4* __restrict__ x1,
                                                const float4* __restrict__ x2,
                                                const float* __restrict__ mask) {
    int ch = blockIdx.x;            // 0..511  (b*128 + c)
    int b  = ch >> 7;
    const float4* p1 = x1 + (size_t)ch * (HW / 4);
    const float4* p2 = x2 + (size_t)ch * (HW / 4);
    const float*  mb = mask + b * MHW;
    int t = threadIdx.x;

    float a1 = 0, b1 = 0, c1 = 0, a1o = 0, b1o = 0, c1o = 0;
    float a2 = 0, b2 = 0, c2 = 0, a2o = 0, b2o = 0, c2o = 0;

#pragma unroll 4
    for (int k = 0; k < 64; k++) {
        int q = t + k * 256;                       // float4 index within channel
        float4 v1 = p1[q];
        float4 v2 = p2[q];
        // pixel p = 4q; h = q>>6; mask row = q>>7; mask col = (2q) mod 128 (even)
        int midx = ((q >> 7) << 7) | ((2 * q) & 126);
        float2 mp = *reinterpret_cast<const float2*>(mb + midx);
        float mv[4]  = {mp.x, mp.x, mp.y, mp.y};
        float xv1[4] = {v1.x, v1.y, v1.z, v1.w};
        float xv2[4] = {v2.x, v2.y, v2.z, v2.w};
#pragma unroll
        for (int i = 0; i < 4; i++) {
            float m = mv[i], om = 1.0f - m;
            float mm = m * m, omm = om * om;
            float x = xv1[i];
            a1  += x * m;   float tt = x * mm;  b1  += tt * m;  c1  += tt * tt;
            a1o += x * om;  float t2 = x * omm; b1o += t2 * om; c1o += t2 * t2;
            x = xv2[i];
            a2  += x * m;   tt = x * mm;        b2  += tt * m;  c2  += tt * tt;
            a2o += x * om;  t2 = x * omm;       b2o += t2 * om; c2o += t2 * t2;
        }
    }

    float vals[12] = {a1, b1, c1, a1o, b1o, c1o, a2, b2, c2, a2o, b2o, c2o};
    __shared__ float red[12][8];
    int lane = t & 31, wid = t >> 5;
#pragma unroll
    for (int i = 0; i < 12; i++) {
        float s = warpSum(vals[i]);
        if (lane == 0) red[i][wid] = s;
    }
    __syncthreads();
    if (wid == 0) {
#pragma unroll
        for (int i = 0; i < 12; i++) {
            float s = (lane < 8) ? red[i][lane] : 0.f;
            s = warpSum(s);
            if (lane == 0) g_sums[ch * 12 + i] = s;
        }
    }
}

// ---------------------------------------------------------------------------
// Kernel 2: one block per batch. Mask sums (exact: upsample is a 2x2 repeat,
// so Sum_HW m = 4*Sum mask, Sum_HW m^2 = 4*Sum mask^2), per-channel stats,
// the four 2C->C modulation GEMVs, and the final per-channel coefficients:
//   out = x1*(m^2*P + om^2*Q) + k1*m + k2*om
// ---------------------------------------------------------------------------
__global__ __launch_bounds__(256) void k_stats(const float* __restrict__ mask,
                                               const float* __restrict__ w_in_mean,
                                               const float* __restrict__ w_in_var,
                                               const float* __restrict__ w_out_mean,
                                               const float* __restrict__ w_out_var) {
    int b = blockIdx.x;
    int t = threadIdx.x;
    int lane = t & 31, wid = t >> 5;

    __shared__ float sred[2][8];
    const float* mb = mask + b * MHW;
    float s1 = 0, s2 = 0;
    for (int i = t; i < MHW; i += 256) { float m = mb[i]; s1 += m; s2 += m * m; }
    s1 = warpSum(s1); s2 = warpSum(s2);
    if (lane == 0) { sred[0][wid] = s1; sred[1][wid] = s2; }
    __syncthreads();

    __shared__ float sh_nin, sh_nout, sh_M2, sh_M2o;
    if (t == 0) {
        float S1 = 0, S2 = 0;
        for (int i = 0; i < 8; i++) { S1 += sred[0][i]; S2 += sred[1][i]; }
        float msum = 4.f * S1, m2sum = 4.f * S2;
        sh_nin  = msum + EPS;
        sh_nout = ((float)HW - msum) + EPS;
        sh_M2   = m2sum;
        sh_M2o  = (float)HW - 2.f * msum + m2sum;   // Sum (1-m)^2
    }
    __syncthreads();

    __shared__ float v_in_mean[2 * CN], v_in_var[2 * CN], v_out_mean[2 * CN], v_out_var[2 * CN];
    __shared__ float mu_in[CN], r_in[CN], mu_out[CN], r_out[CN];
    {
        int c = t & 127;
        int isx2 = t >> 7;                 // t<128: x1 stats; t>=128: x2 stats
        const float* s = g_sums + (size_t)(b * CN + c) * 12 + isx2 * 6;
        float A = s[0], Bb = s[1], Cc = s[2], Ao = s[3], Bo = s[4], Co = s[5];
        float mean_in = A / sh_nin;
        float var_in = (Cc - 2.f * mean_in * Bb + mean_in * mean_in * sh_M2) / sh_nin;
        var_in = fmaxf(var_in, 0.f);
        float mean_out = Ao / sh_nout;
        float var_out = (Co - 2.f * mean_out * Bo + mean_out * mean_out * sh_M2o) / sh_nout;
        var_out = fmaxf(var_out, 0.f);
        v_in_mean[t] = mean_in;  v_in_var[t] = var_in;
        v_out_mean[t] = mean_out; v_out_var[t] = var_out;
        if (!isx2) {
            mu_in[c] = mean_in;   r_in[c] = rsqrtf(var_in + EPS);
            mu_out[c] = mean_out; r_out[c] = rsqrtf(var_out + EPS);
        }
    }
    __syncthreads();

    __shared__ float ada[4][CN];
    {
        const float* wmats[4] = {w_in_mean, w_in_var, w_out_mean, w_out_var};
        const float* vvec[4]  = {v_in_mean, v_in_var, v_out_mean, v_out_var};
        for (int id = t; id < 4 * CN; id += 256) {
            int mat = id >> 7, c = id & 127;
            const float* wrow = wmats[mat] + (size_t)c * 2 * CN;
            const float* v = vvec[mat];
            float acc = 0.f;
#pragma unroll 8
            for (int j = 0; j < 2 * CN; j++) acc += wrow[j] * v[j];
            ada[mat][c] = acc;
        }
    }
    __syncthreads();

    if (t < CN) {
        int c = t;
        float P  = r_in[c]  * ada[1][c];
        float Q  = r_out[c] * ada[3][c];
        float k1 = ada[0][c] - mu_in[c]  * P;
        float k2 = ada[2][c] - mu_out[c] * Q;
        reinterpret_cast<float4*>(g_coef)[b * CN + c] = make_float4(P, Q, k1, k2);
    }
}

// ---------------------------------------------------------------------------
// Kernel 3: elementwise apply. out = x1*(m^2*P + om^2*Q) + k1*m + k2*om
// ---------------------------------------------------------------------------
__global__ __launch_bounds__(256) void k_apply(const float4* __restrict__ x1,
                                               const float* __restrict__ mask,
                                               float4* __restrict__ out) {
    int ch = blockIdx.y;
    int b = ch >> 7;
    float4 coef = __ldg(&reinterpret_cast<const float4*>(g_coef)[ch]);
    float P = coef.x, Q = coef.y, k1 = coef.z, k2 = coef.w;
    const float* mb = mask + b * MHW;

    int q = blockIdx.x * 256 + threadIdx.x;     // float4 index within channel
    float4 v = x1[(size_t)ch * (HW / 4) + q];
    int midx = ((q >> 7) << 7) | ((2 * q) & 126);
    float2 mp = *reinterpret_cast<const float2*>(mb + midx);
    float xs[4] = {v.x, v.y, v.z, v.w};
    float ms[4] = {mp.x, mp.x, mp.y, mp.y};
    float os[4];
#pragma unroll
    for (int i = 0; i < 4; i++) {
        float m = ms[i], om = 1.f - m;
        float s = m * m * P + om * om * Q;
        os[i] = xs[i] * s + k1 * m + k2 * om;
    }
    out[(size_t)ch * (HW / 4) + q] = make_float4(os[0], os[1], os[2], os[3]);
}

extern "C" void kernel_launch(void* const* d_in, const int* in_sizes, int n_in,
                              void* d_out, int out_size) {
    const float* x1         = (const float*)d_in[0];
    const float* x2         = (const float*)d_in[1];
    const float* mask       = (const float*)d_in[2];
    const float* w_in_mean  = (const float*)d_in[3];
    const float* w_in_var   = (const float*)d_in[4];
    const float* w_out_mean = (const float*)d_in[5];
    const float* w_out_var  = (const float*)d_in[6];
    float* out = (float*)d_out;

    k_reduce<<<NCH, 256>>>((const float4*)x1, (const float4*)x2, mask);
    k_stats<<<BN, 256>>>(mask, w_in_mean, w_in_var, w_out_mean, w_out_var);
    k_apply<<<dim3(HW / 4 / 256, NCH), 256>>>((const float4*)x1, mask, (float4*)out);
}

// round 2
// speedup vs baseline: 1.5248x; 1.5248x over previous
#include <cuda_runtime.h>

#define EPS 1e-8f
#define BN 4
#define CN 128
#define HN 256
#define WN 256
#define HW (HN*WN)       // 65536
#define NCH (BN*CN)      // 512
#define MHW (128*128)    // 16384
#define NPART 4

// Scratch: per-channel partial sums (4 parts), stats vectors, coefficients.
__device__ float g_sums[NPART * NCH * 12];
__device__ float g_v[BN * 4 * 256];     // per batch: [in_mean|in_var|out_mean|out_var] each 256 (=x1||x2)
__device__ float g_mr[BN * 512];        // per batch: mu_in(128), r_in(128), mu_out(128), r_out(128)
__device__ float g_coef[NCH * 4];       // per channel: P, Q, k1, k2

__device__ __forceinline__ float warpSum(float v) {
#pragma unroll
    for (int o = 16; o; o >>= 1) v += __shfl_xor_sync(0xffffffffu, v, o);
    return v;
}

// ---------------------------------------------------------------------------
// Kernel 1: per-(b,c) partial reductions over a quarter of HW.
// grid = NPART * NCH (part-major). Accumulates, per tensor/region:
//   A = sum x*m, B = sum x*m^3, C = sum x^2*m^4
// ---------------------------------------------------------------------------
__global__ __launch_bounds__(256) void k_reduce(const float4* __restrict__ x1,
                                                const float4* __restrict__ x2,
                                                const float* __restrict__ mask) {
    int ch   = blockIdx.x & (NCH - 1);
    int part = blockIdx.x >> 9;
    int b  = ch >> 7;
    const float4* p1 = x1 + (size_t)ch * (HW / 4) + part * 4096;
    const float4* p2 = x2 + (size_t)ch * (HW / 4) + part * 4096;
    const float*  mb = mask + b * MHW;
    int t = threadIdx.x;
    int qbase = part * 4096;

    float a1 = 0, b1 = 0, c1 = 0, a1o = 0, b1o = 0, c1o = 0;
    float a2 = 0, b2 = 0, c2 = 0, a2o = 0, b2o = 0, c2o = 0;

#pragma unroll 4
    for (int k = 0; k < 16; k++) {
        int qi = t + k * 256;                     // local float4 index
        float4 v1 = p1[qi];
        float4 v2 = p2[qi];
        int q = qbase + qi;
        // pixel p = 4q; mask row = q>>7; mask col = (2q) & 126
        int midx = ((q >> 7) << 7) | ((2 * q) & 126);
        float2 mp = *reinterpret_cast<const float2*>(mb + midx);
        float mv[4]  = {mp.x, mp.x, mp.y, mp.y};
        float xv1[4] = {v1.x, v1.y, v1.z, v1.w};
        float xv2[4] = {v2.x, v2.y, v2.z, v2.w};
#pragma unroll
        for (int i = 0; i < 4; i++) {
            float m = mv[i], om = 1.0f - m;
            float mm = m * m, omm = om * om;
            float x = xv1[i];
            a1  += x * m;   float tt = x * mm;  b1  += tt * m;  c1  += tt * tt;
            a1o += x * om;  float t2 = x * omm; b1o += t2 * om; c1o += t2 * t2;
            x = xv2[i];
            a2  += x * m;   tt = x * mm;        b2  += tt * m;  c2  += tt * tt;
            a2o += x * om;  t2 = x * omm;       b2o += t2 * om; c2o += t2 * t2;
        }
    }

    float vals[12] = {a1, b1, c1, a1o, b1o, c1o, a2, b2, c2, a2o, b2o, c2o};
    __shared__ float red[12][8];
    int lane = t & 31, wid = t >> 5;
#pragma unroll
    for (int i = 0; i < 12; i++) {
        float s = warpSum(vals[i]);
        if (lane == 0) red[i][wid] = s;
    }
    __syncthreads();
    if (wid == 0) {
#pragma unroll
        for (int i = 0; i < 12; i++) {
            float s = (lane < 8) ? red[i][lane] : 0.f;
            s = warpSum(s);
            if (lane == 0) g_sums[(size_t)(part * NCH + ch) * 12 + i] = s;
        }
    }
}

// ---------------------------------------------------------------------------
// Kernel 2: one block per batch. Mask sums (exact: 2x2 repeat upsample =>
// Sum m = 4*Sum mask, Sum m^2 = 4*Sum mask^2), combine partials, per-channel
// mean/var; emit modulation input vectors g_v and mu/rsqrt table g_mr.
// ---------------------------------------------------------------------------
__global__ __launch_bounds__(256) void k_stats(const float* __restrict__ mask) {
    int b = blockIdx.x;
    int t = threadIdx.x;
    int lane = t & 31, wid = t >> 5;

    __shared__ float sred[2][8];
    const float* mb = mask + b * MHW;
    float s1 = 0, s2 = 0;
    for (int i = t; i < MHW; i += 256) { float m = mb[i]; s1 += m; s2 += m * m; }
    s1 = warpSum(s1); s2 = warpSum(s2);
    if (lane == 0) { sred[0][wid] = s1; sred[1][wid] = s2; }

    // combine the 4 partial sums: 128 channels * 12 stats
    __shared__ float ssum[CN * 12];
    for (int id = t; id < CN * 12; id += 256) {
        int c = id / 12, i = id - c * 12;
        float v = 0.f;
#pragma unroll
        for (int p = 0; p < NPART; p++)
            v += g_sums[(size_t)(p * NCH + b * CN + c) * 12 + i];
        ssum[id] = v;
    }
    __syncthreads();

    __shared__ float sh_nin, sh_nout, sh_M2, sh_M2o;
    if (t == 0) {
        float S1 = 0, S2 = 0;
        for (int i = 0; i < 8; i++) { S1 += sred[0][i]; S2 += sred[1][i]; }
        float msum = 4.f * S1, m2sum = 4.f * S2;
        sh_nin  = msum + EPS;
        sh_nout = ((float)HW - msum) + EPS;
        sh_M2   = m2sum;
        sh_M2o  = (float)HW - 2.f * msum + m2sum;   // Sum (1-m)^2
    }
    __syncthreads();

    {
        int c = t & 127;
        int isx2 = t >> 7;                 // t<128: x1 stats; t>=128: x2 stats
        const float* s = ssum + c * 12 + isx2 * 6;
        float A = s[0], Bb = s[1], Cc = s[2], Ao = s[3], Bo = s[4], Co = s[5];
        float mean_in = A / sh_nin;
        float var_in = (Cc - 2.f * mean_in * Bb + mean_in * mean_in * sh_M2) / sh_nin;
        var_in = fmaxf(var_in, 0.f);
        float mean_out = Ao / sh_nout;
        float var_out = (Co - 2.f * mean_out * Bo + mean_out * mean_out * sh_M2o) / sh_nout;
        var_out = fmaxf(var_out, 0.f);
        float* v = g_v + b * 1024;
        int vi = isx2 * 128 + c;
        v[vi]       = mean_in;
        v[256 + vi] = var_in;
        v[512 + vi] = mean_out;
        v[768 + vi] = var_out;
        if (!isx2) {
            float* mr = g_mr + b * 512;
            mr[c]       = mean_in;
            mr[128 + c] = rsqrtf(var_in + EPS);
            mr[256 + c] = mean_out;
            mr[384 + c] = rsqrtf(var_out + EPS);
        }
    }
}

// ---------------------------------------------------------------------------
// Kernel 3: modulation GEMVs (coalesced, warp-per-row) + final coefficients.
// grid = (BN, 4 channel-groups), 256 threads (8 warps * 16 rows each).
//   out = x1*(m^2*P + om^2*Q) + k1*m + k2*om
// ---------------------------------------------------------------------------
__global__ __launch_bounds__(256) void k_gemv(const float* __restrict__ w_in_mean,
                                              const float* __restrict__ w_in_var,
                                              const float* __restrict__ w_out_mean,
                                              const float* __restrict__ w_out_var) {
    int b  = blockIdx.x;
    int cg = blockIdx.y;          // channel group: rows [cg*32, cg*32+32)
    int t = threadIdx.x;
    int lane = t & 31, wid = t >> 5;

    __shared__ float v_sh[4 * 256];
    for (int id = t; id < 1024; id += 256) v_sh[id] = g_v[b * 1024 + id];
    __shared__ float ada_sh[128];          // [mat*32 + local_row]
    __syncthreads();

    const float* wmats[4] = {w_in_mean, w_in_var, w_out_mean, w_out_var};
#pragma unroll
    for (int it = 0; it < 16; it++) {
        int task = wid * 16 + it;          // 0..127 == mat*32 + lr
        int mat = task >> 5, lr = task & 31;
        const float* wrow = wmats[mat] + (size_t)(cg * 32 + lr) * 256;
        const float* vv = v_sh + mat * 256;
        float acc = 0.f;
#pragma unroll
        for (int j = 0; j < 8; j++)
            acc = fmaf(wrow[lane + 32 * j], vv[lane + 32 * j], acc);
        acc = warpSum(acc);
        if (lane == 0) ada_sh[task] = acc;
    }
    __syncthreads();

    if (t < 32) {
        int c = cg * 32 + t;
        const float* mr = g_mr + b * 512;
        float mu_i = mr[c], r_i = mr[128 + c], mu_o = mr[256 + c], r_o = mr[384 + c];
        float P  = r_i * ada_sh[32 + t];          // in_var
        float Q  = r_o * ada_sh[96 + t];          // out_var
        float k1 = ada_sh[t]      - mu_i * P;     // in_mean
        float k2 = ada_sh[64 + t] - mu_o * Q;     // out_mean
        reinterpret_cast<float4*>(g_coef)[b * CN + c] = make_float4(P, Q, k1, k2);
    }
}

// ---------------------------------------------------------------------------
// Kernel 4: elementwise apply, 2 float4 per thread.
// out = x1*(m^2*P + om^2*Q) + k1*m + k2*om
// ---------------------------------------------------------------------------
__global__ __launch_bounds__(256) void k_apply(const float4* __restrict__ x1,
                                               const float* __restrict__ mask,
                                               float4* __restrict__ out) {
    int ch = blockIdx.y;
    int b = ch >> 7;
    float4 coef = __ldg(&reinterpret_cast<const float4*>(g_coef)[ch]);
    float P = coef.x, Q = coef.y, k1 = coef.z, k2 = coef.w;
    const float* mb = mask + b * MHW;
    const float4* px = x1 + (size_t)ch * (HW / 4);
    float4* po = out + (size_t)ch * (HW / 4);
    int q0 = blockIdx.x * 512 + threadIdx.x;

#pragma unroll
    for (int r = 0; r < 2; r++) {
        int q = q0 + r * 256;
        float4 v = px[q];
        int midx = ((q >> 7) << 7) | ((2 * q) & 126);
        float2 mp = *reinterpret_cast<const float2*>(mb + midx);
        float xs[4] = {v.x, v.y, v.z, v.w};
        float ms[4] = {mp.x, mp.x, mp.y, mp.y};
        float os[4];
#pragma unroll
        for (int i = 0; i < 4; i++) {
            float m = ms[i], om = 1.f - m;
            float s = m * m * P + om * om * Q;
            os[i] = xs[i] * s + k1 * m + k2 * om;
        }
        po[q] = make_float4(os[0], os[1], os[2], os[3]);
    }
}

extern "C" void kernel_launch(void* const* d_in, const int* in_sizes, int n_in,
                              void* d_out, int out_size) {
    const float* x1         = (const float*)d_in[0];
    const float* x2         = (const float*)d_in[1];
    const float* mask       = (const float*)d_in[2];
    const float* w_in_mean  = (const float*)d_in[3];
    const float* w_in_var   = (const float*)d_in[4];
    const float* w_out_mean = (const float*)d_in[5];
    const float* w_out_var  = (const float*)d_in[6];
    float* out = (float*)d_out;

    k_reduce<<<NPART * NCH, 256>>>((const float4*)x1, (const float4*)x2, mask);
    k_stats<<<BN, 256>>>(mask);
    k_gemv<<<dim3(BN, 4), 256>>>(w_in_mean, w_in_var, w_out_mean, w_out_var);
    k_apply<<<dim3(HW / 4 / 512, NCH), 256>>>((const float4*)x1, mask, (float4*)out);
}